// round 14
// baseline (speedup 1.0000x reference)
#include <cuda_runtime.h>
#include <cuda_bf16.h>
#include <cuda_fp16.h>
#include <mma.h>

using namespace nvcuda;

#define N_NODES 100000
#define N_EDGES 1600000
#define IN_CH   128
#define OUT_CH  64
#define SCAN_T  512
#define SB ((N_NODES + SCAN_T - 1) / SCAN_T)   /* 196 */
#define EB ((N_EDGES + 255) / 256)             /* 6250 */
#define DB 64                                  /* degree bins */
#define NB ((N_NODES + 1023) / 1024)           /* 98 node blocks */

// ---------------- device scratch (static, allocation-free) ----------------
__device__ float              g_W23[IN_CH * OUT_CH];   // W2@W3   [128,64]
__device__ float              g_Wc[IN_CH * OUT_CH];    // W1@W23  [128,64]
__device__ int                g_rank[N_EDGES];         // edge rank within dst bucket
__device__ int                g_col[N_EDGES];          // src ids grouped by dst
__device__ int                g_off[N_NODES + 1];      // CSR row offsets
__device__ int                g_cnt[N_NODES];          // histogram (cleared by fill)
__device__ unsigned long long g_state[SB];             // lookback state
__device__ int                g_drank[N_NODES];        // node rank within (bin,block)
__device__ int                g_bcnt[DB * NB];         // per-(bin,block) counts
__device__ int                g_bbase[DB * NB];        // scanned bases
__device__ int                g_perm[N_NODES];         // degree-sorted node order
__device__ __half             g_t[N_NODES * OUT_CH];   // ping (fp16 features)
__device__ __half             g_y[N_NODES * OUT_CH];   // pong (fp16 features)

// ---------------- convert: dst-half only -> histogram + rank ----------------
__global__ void k_convert(const void* ei) {
    const int* w = (const int*)ei;
    bool is64 = ((w[1] | w[3] | w[5] | w[7]) == 0);
    int tid = blockIdx.x * blockDim.x + threadIdx.x;
    int stride = gridDim.x * blockDim.x;
    for (int e = tid; e < N_EDGES; e += stride) {
        int d;
        if (is64) d = (int)((const long long*)ei)[(long long)N_EDGES + e];
        else      d = ((const int*)ei)[N_EDGES + e];
        g_rank[e] = atomicAdd(&g_cnt[d], 1);
    }
}

// ---------------- single-pass scan: decoupled lookback ----------------
__global__ void k_scan() {
    __shared__ int s[SCAN_T];
    __shared__ int sh_excl;
    int t = threadIdx.x, b = blockIdx.x;
    int idx = b * SCAN_T + t;
    int v = (idx < N_NODES) ? g_cnt[idx] : 0;
    s[t] = v;
    __syncthreads();
    for (int o = 1; o < SCAN_T; o <<= 1) {
        int a = (t >= o) ? s[t - o] : 0;
        __syncthreads();
        s[t] += a;
        __syncthreads();
    }
    int incl = s[t];
    int total = s[SCAN_T - 1];

    if (t == 0) {
        unsigned long long st = (b == 0)
            ? ((2ULL << 32) | (unsigned long long)(unsigned)total)
            : ((1ULL << 32) | (unsigned long long)(unsigned)total);
        atomicExch(&g_state[b], st);
    }

    if (b == 0) {
        if (t == 0) sh_excl = 0;
    } else if (t < 32) {
        int excl = 0;
        int p = b - 1;
        while (true) {
            int pi = p - t;
            unsigned long long stv;
            if (pi >= 0) {
                do { stv = atomicAdd(&g_state[pi], 0ULL); } while ((stv >> 32) == 0);
            } else {
                stv = (2ULL << 32);
            }
            unsigned flag = (unsigned)(stv >> 32);
            int val = (int)(unsigned)(stv & 0xffffffffULL);
            unsigned done_mask = __ballot_sync(0xffffffffu, flag == 2);
            int k = done_mask ? (__ffs(done_mask) - 1) : 31;
            int contrib = (t <= k) ? val : 0;
#pragma unroll
            for (int o = 16; o > 0; o >>= 1)
                contrib += __shfl_down_sync(0xffffffffu, contrib, o);
            if (t == 0) excl += contrib;
            if (done_mask) break;
            p -= 32;
        }
        if (t == 0) {
            atomicExch(&g_state[b],
                       (2ULL << 32) | (unsigned long long)(unsigned)(excl + total));
            sh_excl = excl;
        }
    }
    __syncthreads();
    int e0 = sh_excl;
    if (idx < N_NODES) g_off[idx] = e0 + incl - v;
    if (b == 0 && t == 0) g_off[N_NODES] = N_EDGES;
}

// ------- atomic-free CSR fill + clear of per-replay state -------
__global__ void k_fill(const void* ei) {
    const int* w = (const int*)ei;
    bool is64 = ((w[1] | w[3] | w[5] | w[7]) == 0);
    int e = blockIdx.x * blockDim.x + threadIdx.x;
    if (e < N_EDGES) {
        int s, d;
        if (is64) {
            const long long* p = (const long long*)ei;
            s = (int)p[e];
            d = (int)p[(long long)N_EDGES + e];
        } else {
            const int* p = (const int*)ei;
            s = p[e];
            d = p[N_EDGES + e];
        }
        g_col[g_off[d] + g_rank[e]] = s;
    }
    if (e < N_NODES) g_cnt[e] = 0;
    if (e < SB) g_state[e] = 0ULL;
}

// ---------------- degree binning: smem hist + local rank ----------------
__global__ __launch_bounds__(1024) void k_dcount() {
    __shared__ int h[DB];
    int t = threadIdx.x, b = blockIdx.x;
    if (t < DB) h[t] = 0;
    __syncthreads();
    int n = b * 1024 + t;
    if (n < N_NODES) {
        int d = min(g_off[n + 1] - g_off[n], DB - 1);
        g_drank[n] = atomicAdd(&h[d], 1);
    }
    __syncthreads();
    if (t < DB) g_bcnt[t * NB + b] = h[t];
}

__global__ __launch_bounds__(1024) void k_dscan2() {
    __shared__ int btot[DB];
    __shared__ int bbase[DB];
    int t = threadIdx.x, lane = t & 31, w = t >> 5;
#pragma unroll
    for (int q = 0; q < 2; q++) {
        int d = 2 * w + q;
        int carry = 0;
        for (int c = 0; c < (NB + 31) / 32; c++) {
            int i = c * 32 + lane;
            int v = (i < NB) ? g_bcnt[d * NB + i] : 0;
            int x = v;
#pragma unroll
            for (int o = 1; o < 32; o <<= 1) {
                int nn = __shfl_up_sync(0xffffffffu, x, o);
                if (lane >= o) x += nn;
            }
            if (i < NB) g_bbase[d * NB + i] = carry + x - v;
            carry += __shfl_sync(0xffffffffu, x, 31);
        }
        if (lane == 0) btot[d] = carry;
    }
    __syncthreads();
    if (w == 0) {
        int carry = 0;
#pragma unroll
        for (int c = 0; c < 2; c++) {
            int i = c * 32 + lane;
            int v = btot[i];
            int x = v;
#pragma unroll
            for (int o = 1; o < 32; o <<= 1) {
                int nn = __shfl_up_sync(0xffffffffu, x, o);
                if (lane >= o) x += nn;
            }
            bbase[i] = carry + x - v;
            carry += __shfl_sync(0xffffffffu, x, 31);
        }
    }
    __syncthreads();
#pragma unroll
    for (int q = 0; q < 2; q++) {
        int d = 2 * w + q;
        int base = bbase[d];
        for (int c = 0; c < (NB + 31) / 32; c++) {
            int i = c * 32 + lane;
            if (i < NB) g_bbase[d * NB + i] += base;
        }
    }
}

__global__ __launch_bounds__(1024) void k_dperm() {
    int t = threadIdx.x, b = blockIdx.x;
    int n = b * 1024 + t;
    if (n < N_NODES) {
        int d = min(g_off[n + 1] - g_off[n], DB - 1);
        g_perm[g_bbase[d * NB + b] + g_drank[n]] = n;
    }
}

// ---------------- weight chain: W23 = W2@W3 ; Wc = W1@W23 ----------------
__global__ void k_w23(const float* __restrict__ W2, const float* __restrict__ W3) {
    int k = blockIdx.x;
    int j = threadIdx.x;
    float s = 0.f;
#pragma unroll 8
    for (int m = 0; m < IN_CH; m++)
        s += W2[k * IN_CH + m] * W3[m * OUT_CH + j];
    g_W23[k * OUT_CH + j] = s;
}
__global__ void k_wc(const float* __restrict__ W1) {
    int k = blockIdx.x;
    int j = threadIdx.x;
    float s = 0.f;
#pragma unroll 8
    for (int m = 0; m < IN_CH; m++)
        s += W1[k * IN_CH + m] * g_W23[m * OUT_CH + j];
    g_Wc[k * OUT_CH + j] = s;
}

// ------- GEMM (tf32 WMMA): t[100000,64] = x[100000,128] @ Wc[128,64], fp16 out
// 64x64 block tile, 4 warps x 16-row stripe; A from gmem (read-once),
// B frags from gmem (g_Wc, L1-resident); 16KB smem for fp32->fp16 epilogue.
// 100000 % 16 == 0 -> every warp stripe is fully in- or out-of-bounds.
#define GM 64
__global__ __launch_bounds__(128) void k_gemm(const float* __restrict__ x) {
    __shared__ float Cs[GM][OUT_CH];   // 16KB epilogue buffer
    int tid = threadIdx.x;
    int wid = tid >> 5;
    int row0 = blockIdx.x * GM;
    int srow = row0 + wid * 16;
    bool active = (srow < N_NODES);    // stripe fully valid (16 | N_NODES)

    if (active) {
        wmma::fragment<wmma::accumulator, 16, 16, 8, float> acc[4];
#pragma unroll
        for (int j = 0; j < 4; j++) wmma::fill_fragment(acc[j], 0.f);

        for (int k = 0; k < IN_CH; k += 8) {
            wmma::fragment<wmma::matrix_a, 16, 16, 8, wmma::precision::tf32,
                           wmma::row_major> a;
            wmma::load_matrix_sync(a, &x[(size_t)srow * IN_CH + k], IN_CH);
#pragma unroll
            for (int t = 0; t < a.num_elements; t++)
                a.x[t] = wmma::__float_to_tf32(a.x[t]);
#pragma unroll
            for (int j = 0; j < 4; j++) {
                wmma::fragment<wmma::matrix_b, 16, 16, 8, wmma::precision::tf32,
                               wmma::row_major> b;
                wmma::load_matrix_sync(b, &g_Wc[k * OUT_CH + j * 16], OUT_CH);
#pragma unroll
                for (int t = 0; t < b.num_elements; t++)
                    b.x[t] = wmma::__float_to_tf32(b.x[t]);
                wmma::mma_sync(acc[j], a, b, acc[j]);
            }
        }
#pragma unroll
        for (int j = 0; j < 4; j++)
            wmma::store_matrix_sync(&Cs[wid * 16][j * 16], acc[j], OUT_CH,
                                    wmma::mem_row_major);
    }
    __syncthreads();

    // epilogue: fp32 -> fp16, vectorized
    for (int i = tid; i < GM * 16; i += 128) {
        int r = i >> 4;
        int c = i & 15;
        int grow = row0 + r;
        if (grow < N_NODES) {
            float4 v = *(float4*)&Cs[r][c * 4];
            __half2 p0 = __floats2half2_rn(v.x, v.y);
            __half2 p1 = __floats2half2_rn(v.z, v.w);
            uint2 u;
            u.x = *(unsigned*)&p0;
            u.y = *(unsigned*)&p1;
            *(uint2*)&g_t[(size_t)grow * OUT_CH + c * 4] = u;
        }
    }
}

// ------- CSR aggregation (fp16 gather, fp32 acc, degree-binned order) -------
__global__ __launch_bounds__(256) void k_agg(int phase, float* __restrict__ out_final) {
    const __half* __restrict__ in = (phase == 1) ? g_y : g_t;
    __half* __restrict__ outh = (phase == 0) ? g_y : g_t;

    int tid = blockIdx.x * blockDim.x + threadIdx.x;
    int p = tid >> 3;
    int l = tid & 7;
    if (p >= N_NODES) return;
    int node = __ldg(&g_perm[p]);      // degree-binned order: uniform warps
    int s = g_off[node];
    int e = g_off[node + 1];
    float acc[8];
#pragma unroll
    for (int q = 0; q < 8; q++) acc[q] = 0.f;

    int i = s;
    for (; i + 8 <= e; i += 8) {
        int c[8];
#pragma unroll
        for (int u = 0; u < 8; u++) c[u] = __ldg(&g_col[i + u]);
        uint4 uu[8];
#pragma unroll
        for (int u = 0; u < 8; u++)
            uu[u] = *(const uint4*)&in[(size_t)c[u] * OUT_CH + l * 8];
#pragma unroll
        for (int u = 0; u < 8; u++) {
            const __half2* h = (const __half2*)&uu[u];
#pragma unroll
            for (int q = 0; q < 4; q++) {
                float2 f = __half22float2(h[q]);
                acc[2 * q + 0] += f.x;
                acc[2 * q + 1] += f.y;
            }
        }
    }
    for (; i + 4 <= e; i += 4) {
        int c[4];
#pragma unroll
        for (int u = 0; u < 4; u++) c[u] = __ldg(&g_col[i + u]);
        uint4 uu[4];
#pragma unroll
        for (int u = 0; u < 4; u++)
            uu[u] = *(const uint4*)&in[(size_t)c[u] * OUT_CH + l * 8];
#pragma unroll
        for (int u = 0; u < 4; u++) {
            const __half2* h = (const __half2*)&uu[u];
#pragma unroll
            for (int q = 0; q < 4; q++) {
                float2 f = __half22float2(h[q]);
                acc[2 * q + 0] += f.x;
                acc[2 * q + 1] += f.y;
            }
        }
    }
    for (; i < e; i++) {
        int c = __ldg(&g_col[i]);
        uint4 u = *(const uint4*)&in[(size_t)c * OUT_CH + l * 8];
        const __half2* h = (const __half2*)&u;
#pragma unroll
        for (int q = 0; q < 4; q++) {
            float2 f = __half22float2(h[q]);
            acc[2 * q + 0] += f.x;
            acc[2 * q + 1] += f.y;
        }
    }

    if (phase < 2) {
        __half2 pk[4];
#pragma unroll
        for (int q = 0; q < 4; q++)
            pk[q] = __floats2half2_rn(acc[2 * q], acc[2 * q + 1]);
        *(uint4*)&outh[(size_t)node * OUT_CH + l * 8] = *(uint4*)pk;
    } else {
        float4 o0 = make_float4(acc[0], acc[1], acc[2], acc[3]);
        float4 o1 = make_float4(acc[4], acc[5], acc[6], acc[7]);
        *(float4*)&out_final[(size_t)node * OUT_CH + l * 8] = o0;
        *(float4*)&out_final[(size_t)node * OUT_CH + l * 8 + 4] = o1;
    }
}

// ---------------- launch: three forked chains inside the captured graph ----
extern "C" void kernel_launch(void* const* d_in, const int* in_sizes, int n_in,
                              void* d_out, int out_size) {
    const float* x  = (const float*)d_in[0];
    const void*  ei = d_in[1];
    const float* W1 = (const float*)d_in[2];
    const float* W2 = (const float*)d_in[3];
    const float* W3 = (const float*)d_in[4];
    float* out = (float*)d_out;

    const int GB = (N_NODES + GM - 1) / GM;          // 1563
    const int AB = (N_NODES * 8 + 255) / 256;        // 3125

    cudaStream_t s2, s3;
    cudaStreamCreateWithFlags(&s2, cudaStreamNonBlocking);
    cudaStreamCreateWithFlags(&s3, cudaStreamNonBlocking);
    cudaEvent_t evF, evJ, evScan, evD;
    cudaEventCreateWithFlags(&evF,    cudaEventDisableTiming);
    cudaEventCreateWithFlags(&evJ,    cudaEventDisableTiming);
    cudaEventCreateWithFlags(&evScan, cudaEventDisableTiming);
    cudaEventCreateWithFlags(&evD,    cudaEventDisableTiming);

    // fork s2 at entry
    cudaEventRecord(evF, 0);
    cudaStreamWaitEvent(s2, evF, 0);

    // ---- chain B on s2: weight chain + tf32 WMMA GEMM ----
    k_w23<<<IN_CH, OUT_CH, 0, s2>>>(W2, W3);
    k_wc<<<IN_CH, OUT_CH, 0, s2>>>(W1);
    k_gemm<<<GB, 128, 0, s2>>>(x);
    cudaEventRecord(evJ, s2);

    // ---- chain A on default stream: CSR build ----
    k_convert<<<2048, 256>>>(ei);
    k_scan<<<SB, SCAN_T>>>();
    cudaEventRecord(evScan, 0);         // g_off ready -> fork degree chain
    k_fill<<<EB, 256>>>(ei);

    // ---- chain C on s3: degree-binned permutation (needs only g_off) ----
    cudaStreamWaitEvent(s3, evScan, 0);
    k_dcount<<<NB, 1024, 0, s3>>>();
    k_dscan2<<<1, 1024, 0, s3>>>();
    k_dperm<<<NB, 1024, 0, s3>>>();
    cudaEventRecord(evD, s3);

    // join: agg needs g_t (B), CSR (A), perm (C)
    cudaStreamWaitEvent(0, evJ, 0);
    cudaStreamWaitEvent(0, evD, 0);

    k_agg<<<AB, 256>>>(0, out);
    k_agg<<<AB, 256>>>(1, out);
    k_agg<<<AB, 256>>>(2, out);

    cudaEventDestroy(evF);
    cudaEventDestroy(evJ);
    cudaEventDestroy(evScan);
    cudaEventDestroy(evD);
    cudaStreamDestroy(s2);
    cudaStreamDestroy(s3);
}

// round 16
// speedup vs baseline: 1.7154x; 1.7154x over previous
#include <cuda_runtime.h>
#include <cuda_bf16.h>
#include <cuda_fp16.h>

#define N_NODES 100000
#define N_EDGES 1600000
#define IN_CH   128
#define OUT_CH  64
#define SCAN_T  512
#define SB ((N_NODES + SCAN_T - 1) / SCAN_T)   /* 196 */
#define EB ((N_EDGES + 255) / 256)             /* 6250 */
#define DB 64                                  /* degree bins */
#define NB ((N_NODES + 1023) / 1024)           /* 98 node blocks */

// ---------------- device scratch (static, allocation-free) ----------------
__device__ float              g_W23[IN_CH * OUT_CH];   // W2@W3   [128,64]
__device__ float              g_Wc[IN_CH * OUT_CH];    // W1@W23  [128,64]
__device__ int                g_rank[N_EDGES];         // edge rank within dst bucket
__device__ int                g_col[N_EDGES];          // src ids grouped by dst
__device__ int                g_off[N_NODES + 1];      // CSR row offsets
__device__ int                g_cnt[N_NODES];          // histogram (cleared by fill)
__device__ unsigned long long g_state[SB];             // lookback state
__device__ int                g_drank[N_NODES];        // node rank within (bin,block)
__device__ int                g_bcnt[DB * NB];         // per-(bin,block) counts
__device__ int                g_bbase[DB * NB];        // scanned bases
__device__ int                g_perm[N_NODES];         // degree-DESC node order (LPT)
__device__ __half             g_t[N_NODES * OUT_CH];   // ping (fp16 features)
__device__ __half             g_y[N_NODES * OUT_CH];   // pong (fp16 features)

// ---------------- convert: dst-half only -> histogram + rank ----------------
__global__ void k_convert(const void* ei) {
    const int* w = (const int*)ei;
    bool is64 = ((w[1] | w[3] | w[5] | w[7]) == 0);
    int tid = blockIdx.x * blockDim.x + threadIdx.x;
    int stride = gridDim.x * blockDim.x;
    for (int e = tid; e < N_EDGES; e += stride) {
        int d;
        if (is64) d = (int)((const long long*)ei)[(long long)N_EDGES + e];
        else      d = ((const int*)ei)[N_EDGES + e];
        g_rank[e] = atomicAdd(&g_cnt[d], 1);
    }
}

// ---------------- single-pass scan: decoupled lookback (shuffle block scan) --
__global__ void k_scan() {
    __shared__ int wsum[16];
    __shared__ int sh_excl;
    int t = threadIdx.x, b = blockIdx.x;
    int lane = t & 31, w = t >> 5;
    int idx = b * SCAN_T + t;
    int v = (idx < N_NODES) ? g_cnt[idx] : 0;

    // warp-inclusive scan
    int xv = v;
#pragma unroll
    for (int o = 1; o < 32; o <<= 1) {
        int n = __shfl_up_sync(0xffffffffu, xv, o);
        if (lane >= o) xv += n;
    }
    if (lane == 31) wsum[w] = xv;
    __syncthreads();
    if (w == 0) {
        int s = (lane < 16) ? wsum[lane] : 0;
#pragma unroll
        for (int o = 1; o < 16; o <<= 1) {
            int n = __shfl_up_sync(0xffffffffu, s, o);
            if (lane >= o) s += n;
        }
        if (lane < 16) wsum[lane] = s;   // inclusive warp totals
    }
    __syncthreads();
    int base = (w > 0) ? wsum[w - 1] : 0;
    int incl = xv + base;                // block-inclusive prefix
    int total = wsum[15];                // block total

    if (t == 0) {
        unsigned long long st = (b == 0)
            ? ((2ULL << 32) | (unsigned long long)(unsigned)total)
            : ((1ULL << 32) | (unsigned long long)(unsigned)total);
        atomicExch(&g_state[b], st);
    }

    if (b == 0) {
        if (t == 0) sh_excl = 0;
    } else if (t < 32) {
        int excl = 0;
        int p = b - 1;
        while (true) {
            int pi = p - t;
            unsigned long long stv;
            if (pi >= 0) {
                do { stv = atomicAdd(&g_state[pi], 0ULL); } while ((stv >> 32) == 0);
            } else {
                stv = (2ULL << 32);
            }
            unsigned flag = (unsigned)(stv >> 32);
            int val = (int)(unsigned)(stv & 0xffffffffULL);
            unsigned done_mask = __ballot_sync(0xffffffffu, flag == 2);
            int k = done_mask ? (__ffs(done_mask) - 1) : 31;
            int contrib = (t <= k) ? val : 0;
#pragma unroll
            for (int o = 16; o > 0; o >>= 1)
                contrib += __shfl_down_sync(0xffffffffu, contrib, o);
            if (t == 0) excl += contrib;
            if (done_mask) break;
            p -= 32;
        }
        if (t == 0) {
            atomicExch(&g_state[b],
                       (2ULL << 32) | (unsigned long long)(unsigned)(excl + total));
            sh_excl = excl;
        }
    }
    __syncthreads();
    int e0 = sh_excl;
    if (idx < N_NODES) g_off[idx] = e0 + incl - v;
    if (b == 0 && t == 0) g_off[N_NODES] = N_EDGES;
}

// ------- atomic-free CSR fill + clear of per-replay state -------
__global__ void k_fill(const void* ei) {
    const int* w = (const int*)ei;
    bool is64 = ((w[1] | w[3] | w[5] | w[7]) == 0);
    int e = blockIdx.x * blockDim.x + threadIdx.x;
    if (e < N_EDGES) {
        int s, d;
        if (is64) {
            const long long* p = (const long long*)ei;
            s = (int)p[e];
            d = (int)p[(long long)N_EDGES + e];
        } else {
            const int* p = (const int*)ei;
            s = p[e];
            d = p[N_EDGES + e];
        }
        g_col[g_off[d] + g_rank[e]] = s;
    }
    if (e < N_NODES) g_cnt[e] = 0;
    if (e < SB) g_state[e] = 0ULL;
}

// ---------------- degree binning: smem hist + local rank ----------------
__global__ __launch_bounds__(1024) void k_dcount() {
    __shared__ int h[DB];
    int t = threadIdx.x, b = blockIdx.x;
    if (t < DB) h[t] = 0;
    __syncthreads();
    int n = b * 1024 + t;
    if (n < N_NODES) {
        int d = min(g_off[n + 1] - g_off[n], DB - 1);
        g_drank[n] = atomicAdd(&h[d], 1);
    }
    __syncthreads();
    if (t < DB) g_bcnt[t * NB + b] = h[t];
}

__global__ __launch_bounds__(1024) void k_dscan2() {
    __shared__ int btot[DB];
    __shared__ int bbase[DB];
    int t = threadIdx.x, lane = t & 31, w = t >> 5;
#pragma unroll
    for (int q = 0; q < 2; q++) {
        int d = 2 * w + q;
        int carry = 0;
        for (int c = 0; c < (NB + 31) / 32; c++) {
            int i = c * 32 + lane;
            int v = (i < NB) ? g_bcnt[d * NB + i] : 0;
            int x = v;
#pragma unroll
            for (int o = 1; o < 32; o <<= 1) {
                int nn = __shfl_up_sync(0xffffffffu, x, o);
                if (lane >= o) x += nn;
            }
            if (i < NB) g_bbase[d * NB + i] = carry + x - v;
            carry += __shfl_sync(0xffffffffu, x, 31);
        }
        if (lane == 0) btot[d] = carry;
    }
    __syncthreads();
    if (w == 0) {
        int carry = 0;
#pragma unroll
        for (int c = 0; c < 2; c++) {
            int i = c * 32 + lane;
            int v = btot[i];
            int x = v;
#pragma unroll
            for (int o = 1; o < 32; o <<= 1) {
                int nn = __shfl_up_sync(0xffffffffu, x, o);
                if (lane >= o) x += nn;
            }
            bbase[i] = carry + x - v;
            carry += __shfl_sync(0xffffffffu, x, 31);
        }
    }
    __syncthreads();
#pragma unroll
    for (int q = 0; q < 2; q++) {
        int d = 2 * w + q;
        int base = bbase[d];
        for (int c = 0; c < (NB + 31) / 32; c++) {
            int i = c * 32 + lane;
            if (i < NB) g_bbase[d * NB + i] += base;
        }
    }
}

// LPT order: reverse the ascending-bin layout so HIGHEST degree nodes come
// first -> heavy work lands in the first scheduling wave of each agg pass.
__global__ __launch_bounds__(1024) void k_dperm() {
    int t = threadIdx.x, b = blockIdx.x;
    int n = b * 1024 + t;
    if (n < N_NODES) {
        int d = min(g_off[n + 1] - g_off[n], DB - 1);
        int pos = g_bbase[d * NB + b] + g_drank[n];
        g_perm[N_NODES - 1 - pos] = n;
    }
}

// ---------------- weight chain: W23 = W2@W3 ; Wc = W1@W23 ----------------
__global__ void k_w23(const float* __restrict__ W2, const float* __restrict__ W3) {
    int k = blockIdx.x;
    int j = threadIdx.x;
    float s = 0.f;
#pragma unroll 8
    for (int m = 0; m < IN_CH; m++)
        s += W2[k * IN_CH + m] * W3[m * OUT_CH + j];
    g_W23[k * OUT_CH + j] = s;
}
__global__ void k_wc(const float* __restrict__ W1) {
    int k = blockIdx.x;
    int j = threadIdx.x;
    float s = 0.f;
#pragma unroll 8
    for (int m = 0; m < IN_CH; m++)
        s += W1[k * IN_CH + m] * g_W23[m * OUT_CH + j];
    g_Wc[k * OUT_CH + j] = s;
}

// ---------------- GEMM (R11 known-good fp32 SIMT): t = x @ Wc, fp16 out ------
#define GM 64
#define GK 64
__global__ __launch_bounds__(256) void k_gemm(const float* __restrict__ x) {
    __shared__ float XsT[GK][GM + 4];
    __shared__ float Ws[GK][OUT_CH];
    int row0 = blockIdx.x * GM;
    int tid = threadIdx.x;
    int ty = tid >> 4;
    int tx = tid & 15;
    float acc[4][4];
#pragma unroll
    for (int i = 0; i < 4; i++)
#pragma unroll
        for (int j = 0; j < 4; j++) acc[i][j] = 0.f;

    for (int kc = 0; kc < IN_CH; kc += GK) {
#pragma unroll
        for (int i = 0; i < 4; i++) {
            int slot = tid + i * 256;
            int r = slot >> 4;
            int kq = slot & 15;
            int grow = row0 + r;
            float4 v = make_float4(0.f, 0.f, 0.f, 0.f);
            if (grow < N_NODES)
                v = *(const float4*)&x[(long long)grow * IN_CH + kc + kq * 4];
            XsT[kq * 4 + 0][r] = v.x;
            XsT[kq * 4 + 1][r] = v.y;
            XsT[kq * 4 + 2][r] = v.z;
            XsT[kq * 4 + 3][r] = v.w;
        }
#pragma unroll
        for (int i = 0; i < 4; i++) {
            int slot = tid + i * 256;
            int k = slot >> 4;
            int nq = slot & 15;
            *(float4*)&Ws[k][nq * 4] =
                *(const float4*)&g_Wc[(kc + k) * OUT_CH + nq * 4];
        }
        __syncthreads();
#pragma unroll
        for (int k = 0; k < GK; k++) {
            float4 a = *(const float4*)&XsT[k][ty * 4];
            float4 b = *(const float4*)&Ws[k][tx * 4];
            float ar[4] = {a.x, a.y, a.z, a.w};
            float br[4] = {b.x, b.y, b.z, b.w};
#pragma unroll
            for (int i = 0; i < 4; i++)
#pragma unroll
                for (int j = 0; j < 4; j++) acc[i][j] += ar[i] * br[j];
        }
        __syncthreads();
    }
#pragma unroll
    for (int i = 0; i < 4; i++) {
        int grow = row0 + ty * 4 + i;
        if (grow < N_NODES) {
            __half2 p[2];
            p[0] = __floats2half2_rn(acc[i][0], acc[i][1]);
            p[1] = __floats2half2_rn(acc[i][2], acc[i][3]);
            *(uint2*)&g_t[(size_t)grow * OUT_CH + tx * 4] = *(uint2*)p;
        }
    }
}

// ------- CSR aggregation (fp16 gather, fp32 acc, LPT degree order) -------
__global__ __launch_bounds__(256) void k_agg(int phase, float* __restrict__ out_final) {
    const __half* __restrict__ in = (phase == 1) ? g_y : g_t;
    __half* __restrict__ outh = (phase == 0) ? g_y : g_t;

    int tid = blockIdx.x * blockDim.x + threadIdx.x;
    int p = tid >> 3;
    int l = tid & 7;
    if (p >= N_NODES) return;
    int node = __ldg(&g_perm[p]);
    int s = g_off[node];
    int e = g_off[node + 1];
    float acc[8];
#pragma unroll
    for (int q = 0; q < 8; q++) acc[q] = 0.f;

    int i = s;
    for (; i + 8 <= e; i += 8) {
        int c[8];
#pragma unroll
        for (int u = 0; u < 8; u++) c[u] = __ldg(&g_col[i + u]);
        uint4 uu[8];
#pragma unroll
        for (int u = 0; u < 8; u++)
            uu[u] = *(const uint4*)&in[(size_t)c[u] * OUT_CH + l * 8];
#pragma unroll
        for (int u = 0; u < 8; u++) {
            const __half2* h = (const __half2*)&uu[u];
#pragma unroll
            for (int q = 0; q < 4; q++) {
                float2 f = __half22float2(h[q]);
                acc[2 * q + 0] += f.x;
                acc[2 * q + 1] += f.y;
            }
        }
    }
    for (; i + 4 <= e; i += 4) {
        int c[4];
#pragma unroll
        for (int u = 0; u < 4; u++) c[u] = __ldg(&g_col[i + u]);
        uint4 uu[4];
#pragma unroll
        for (int u = 0; u < 4; u++)
            uu[u] = *(const uint4*)&in[(size_t)c[u] * OUT_CH + l * 8];
#pragma unroll
        for (int u = 0; u < 4; u++) {
            const __half2* h = (const __half2*)&uu[u];
#pragma unroll
            for (int q = 0; q < 4; q++) {
                float2 f = __half22float2(h[q]);
                acc[2 * q + 0] += f.x;
                acc[2 * q + 1] += f.y;
            }
        }
    }
    for (; i < e; i++) {
        int c = __ldg(&g_col[i]);
        uint4 u = *(const uint4*)&in[(size_t)c * OUT_CH + l * 8];
        const __half2* h = (const __half2*)&u;
#pragma unroll
        for (int q = 0; q < 4; q++) {
            float2 f = __half22float2(h[q]);
            acc[2 * q + 0] += f.x;
            acc[2 * q + 1] += f.y;
        }
    }

    if (phase < 2) {
        __half2 pk[4];
#pragma unroll
        for (int q = 0; q < 4; q++)
            pk[q] = __floats2half2_rn(acc[2 * q], acc[2 * q + 1]);
        *(uint4*)&outh[(size_t)node * OUT_CH + l * 8] = *(uint4*)pk;
    } else {
        float4 o0 = make_float4(acc[0], acc[1], acc[2], acc[3]);
        float4 o1 = make_float4(acc[4], acc[5], acc[6], acc[7]);
        *(float4*)&out_final[(size_t)node * OUT_CH + l * 8] = o0;
        *(float4*)&out_final[(size_t)node * OUT_CH + l * 8 + 4] = o1;
    }
}

// ---------------- launch: three forked chains inside the captured graph ----
extern "C" void kernel_launch(void* const* d_in, const int* in_sizes, int n_in,
                              void* d_out, int out_size) {
    const float* x  = (const float*)d_in[0];
    const void*  ei = d_in[1];
    const float* W1 = (const float*)d_in[2];
    const float* W2 = (const float*)d_in[3];
    const float* W3 = (const float*)d_in[4];
    float* out = (float*)d_out;

    const int GB = (N_NODES + GM - 1) / GM;          // 1563
    const int AB = (N_NODES * 8 + 255) / 256;        // 3125

    cudaStream_t s2, s3;
    cudaStreamCreateWithFlags(&s2, cudaStreamNonBlocking);
    cudaStreamCreateWithFlags(&s3, cudaStreamNonBlocking);
    cudaEvent_t evF, evJ, evScan, evD;
    cudaEventCreateWithFlags(&evF,    cudaEventDisableTiming);
    cudaEventCreateWithFlags(&evJ,    cudaEventDisableTiming);
    cudaEventCreateWithFlags(&evScan, cudaEventDisableTiming);
    cudaEventCreateWithFlags(&evD,    cudaEventDisableTiming);

    // fork s2 at entry
    cudaEventRecord(evF, 0);
    cudaStreamWaitEvent(s2, evF, 0);

    // ---- chain B on s2: weight chain + fp32 GEMM ----
    k_w23<<<IN_CH, OUT_CH, 0, s2>>>(W2, W3);
    k_wc<<<IN_CH, OUT_CH, 0, s2>>>(W1);
    k_gemm<<<GB, 256, 0, s2>>>(x);
    cudaEventRecord(evJ, s2);

    // ---- chain A on default stream: CSR build ----
    k_convert<<<2048, 256>>>(ei);
    k_scan<<<SB, SCAN_T>>>();
    cudaEventRecord(evScan, 0);         // g_off ready -> fork degree chain
    k_fill<<<EB, 256>>>(ei);

    // ---- chain C on s3: degree-binned LPT permutation (needs only g_off) ----
    cudaStreamWaitEvent(s3, evScan, 0);
    k_dcount<<<NB, 1024, 0, s3>>>();
    k_dscan2<<<1, 1024, 0, s3>>>();
    k_dperm<<<NB, 1024, 0, s3>>>();
    cudaEventRecord(evD, s3);

    // join: agg needs g_t (B), CSR (A), perm (C)
    cudaStreamWaitEvent(0, evJ, 0);
    cudaStreamWaitEvent(0, evD, 0);

    k_agg<<<AB, 256>>>(0, out);
    k_agg<<<AB, 256>>>(1, out);
    k_agg<<<AB, 256>>>(2, out);

    cudaEventDestroy(evF);
    cudaEventDestroy(evJ);
    cudaEventDestroy(evScan);
    cudaEventDestroy(evD);
    cudaStreamDestroy(s2);
    cudaStreamDestroy(s3);
}